// round 1
// baseline (speedup 1.0000x reference)
#include <cuda_runtime.h>
#include <cstdint>

// Problem constants (fixed by reference)
#define NB 4096
#define NN 128
#define NH 32
#define WARPS_PER_CTA 8

// Bit-packed adjacency: for each (b, node), 128 bits over d = parents mask.
// g_packed[(b*128 + node)*4 + w] bit j  <=>  A[b, w*32+j, node] != 0
__device__ unsigned int g_packed[(size_t)NB * NN * 4];

// ---------------------------------------------------------------------------
// Kernel 1: bit-pack A (coalesced read of 256MB, write 8MB)
// block = 128 threads (node dim), grid = B*4 (b, word)
// ---------------------------------------------------------------------------
__global__ void pack_kernel(const float* __restrict__ A) {
    int node = threadIdx.x;            // 0..127, lanes -> consecutive addresses
    int bw   = blockIdx.x;
    int b    = bw >> 2;
    int w    = bw & 3;
    const float* Ab = A + (size_t)b * NN * NN;
    unsigned int word = 0;
#pragma unroll
    for (int j = 0; j < 32; j++) {
        float v = __ldg(&Ab[(size_t)(w * 32 + j) * NN + node]);
        word |= (v != 0.0f ? 1u : 0u) << j;
    }
    g_packed[((size_t)(b * NN + node) << 2) + w] = word;
}

// ---------------------------------------------------------------------------
// Kernel 2: sequential per-batch evaluation. One warp per batch element.
// lane = hidden channel (H=32). Sparse active-parent compaction per step.
// ---------------------------------------------------------------------------
__global__ __launch_bounds__(WARPS_PER_CTA * 32)
void chain_kernel(const float* __restrict__ x,
                  const float* __restrict__ u,
                  const float* __restrict__ W1,   // (128,129,32)
                  const float* __restrict__ b1,   // (128,32)
                  const float* __restrict__ W2,   // (128,32,1)
                  const float* __restrict__ b2,   // (128,1)
                  const int*   __restrict__ order,   // (B,128)
                  const int*   __restrict__ do_idxs, // (B,)
                  float* __restrict__ out,        // (B,128)
                  int B)
{
    __shared__ float          s_out [WARPS_PER_CTA][NN];
    __shared__ unsigned short s_list[WARPS_PER_CTA][NN];
    __shared__ int            s_ord [WARPS_PER_CTA][NN];

    const int warp = threadIdx.x >> 5;
    const int lane = threadIdx.x & 31;
    const int b    = blockIdx.x * WARPS_PER_CTA + warp;
    if (b >= B) return;

    float*          so   = s_out[warp];
    unsigned short* sl   = s_list[warp];
    int*            sord = s_ord[warp];

    const int   do_idx = do_idxs[b];
    const float ub     = u[b];
    const float* xb    = x + (size_t)b * NN;

    // init outputs (u at do node, else 0) + cache order row in smem
#pragma unroll
    for (int k = 0; k < 4; k++) {
        int d = k * 32 + lane;
        so[d]   = (d == do_idx) ? ub : 0.0f;
        sord[d] = order[(size_t)b * NN + d];
    }

    // nonzero-outputs bitmask (maintained uniformly across the warp)
    unsigned int nz0 = 0, nz1 = 0, nz2 = 0, nz3 = 0;
    if (do_idx >= 0) {
        unsigned int bit = 1u << (do_idx & 31);
        if      ((do_idx >> 5) == 0) nz0 = bit;
        else if ((do_idx >> 5) == 1) nz1 = bit;
        else if ((do_idx >> 5) == 2) nz2 = bit;
        else                         nz3 = bit;
    }

    const uint4* pk = reinterpret_cast<const uint4*>(g_packed + (size_t)b * NN * 4);
    const unsigned int lanebit = 1u << lane;
    const unsigned int below   = lanebit - 1u;

    __syncwarp();

    for (int t = 0; t < NN; t++) {
        const int node = sord[t];

        if (node != do_idx) {
            uint4 mw = __ldg(&pk[node]);            // 128-bit parent mask
            unsigned int m0 = mw.x & nz0;
            unsigned int m1 = mw.y & nz1;
            unsigned int m2 = mw.z & nz2;
            unsigned int m3 = mw.w & nz3;

            int c0 = __popc(m0), c1 = __popc(m1), c2 = __popc(m2), c3 = __popc(m3);

            __syncwarp();  // previous step's reads of sl/so done before rewrite
            if (m0 & lanebit) sl[__popc(m0 & below)]                = (unsigned short)lane;
            if (m1 & lanebit) sl[c0 + __popc(m1 & below)]           = (unsigned short)(32 + lane);
            if (m2 & lanebit) sl[c0 + c1 + __popc(m2 & below)]      = (unsigned short)(64 + lane);
            if (m3 & lanebit) sl[c0 + c1 + c2 + __popc(m3 & below)] = (unsigned short)(96 + lane);
            const int cnt = c0 + c1 + c2 + c3;
            __syncwarp();

            const float* w1n = W1 + ((size_t)node * 129) * NH + lane;
            float acc = __ldg(&b1[node * NH + lane])
                      + __ldg(&xb[node]) * __ldg(&w1n[128 * NH]);

            int i = 0;
            for (; i + 4 <= cnt; i += 4) {      // MLP=4: 4 independent L2 loads
                int d0 = sl[i], d1 = sl[i + 1], d2 = sl[i + 2], d3 = sl[i + 3];
                float v0 = __ldg(&w1n[d0 * NH]);
                float v1 = __ldg(&w1n[d1 * NH]);
                float v2 = __ldg(&w1n[d2 * NH]);
                float v3 = __ldg(&w1n[d3 * NH]);
                float o0 = so[d0], o1 = so[d1], o2 = so[d2], o3 = so[d3];
                acc = fmaf(o0, v0, acc);
                acc = fmaf(o1, v1, acc);
                acc = fmaf(o2, v2, acc);
                acc = fmaf(o3, v3, acc);
            }
            for (; i < cnt; i++) {
                int d = sl[i];
                acc = fmaf(so[d], __ldg(&w1n[d * NH]), acc);
            }

            // leaky_relu (slope 0.01), then 32->1 dot via butterfly reduce
            float h = acc > 0.0f ? acc : 0.01f * acc;
            float p = h * __ldg(&W2[node * NH + lane]);
            p += __shfl_xor_sync(0xffffffffu, p, 16);
            p += __shfl_xor_sync(0xffffffffu, p, 8);
            p += __shfl_xor_sync(0xffffffffu, p, 4);
            p += __shfl_xor_sync(0xffffffffu, p, 2);
            p += __shfl_xor_sync(0xffffffffu, p, 1);
            float outv = p + __ldg(&b2[node]);

            if (lane == 0) so[node] = outv;
            __syncwarp();
        }

        // mark node as now-defined (uniform update)
        unsigned int bit = 1u << (node & 31);
        int wsel = node >> 5;
        if      (wsel == 0) nz0 |= bit;
        else if (wsel == 1) nz1 |= bit;
        else if (wsel == 2) nz2 |= bit;
        else                nz3 |= bit;
    }

#pragma unroll
    for (int k = 0; k < 4; k++) {
        int d = k * 32 + lane;
        out[(size_t)b * NN + d] = so[d];
    }
}

// ---------------------------------------------------------------------------
// inputs (metadata order): x, A, u, W1, b1, W2, b2, order, do_idxs
// ---------------------------------------------------------------------------
extern "C" void kernel_launch(void* const* d_in, const int* in_sizes, int n_in,
                              void* d_out, int out_size) {
    const float* x   = (const float*)d_in[0];
    const float* A   = (const float*)d_in[1];
    const float* u   = (const float*)d_in[2];
    const float* W1  = (const float*)d_in[3];
    const float* b1  = (const float*)d_in[4];
    const float* W2  = (const float*)d_in[5];
    const float* b2  = (const float*)d_in[6];
    const int*   ord = (const int*)d_in[7];
    const int*   doi = (const int*)d_in[8];
    float* out = (float*)d_out;

    int B = in_sizes[2];              // size of u = batch
    if (B > NB) B = NB;               // g_packed capacity (fixed problem size)

    pack_kernel<<<B * 4, 128>>>(A);

    int grid = (B + WARPS_PER_CTA - 1) / WARPS_PER_CTA;
    chain_kernel<<<grid, WARPS_PER_CTA * 32>>>(x, u, W1, b1, W2, b2, ord, doi, out, B);
}

// round 2
// speedup vs baseline: 1.2900x; 1.2900x over previous
#include <cuda_runtime.h>
#include <cstdint>

// Problem constants (fixed by reference)
#define NB 4096
#define NN 128
#define NH 32
#define WARPS_PER_CTA 8

// Bit-packed adjacency: for each (b, node), 128 bits over d = parents mask.
// g_packed[(b*128 + node)*4 + w] bit j  <=>  A[b, w*32+j, node] != 0
__device__ unsigned int g_packed[(size_t)NB * NN * 4];

// ---------------------------------------------------------------------------
// Kernel 1: bit-pack A (coalesced read of 256MB, write 8MB). HBM-bound.
// ---------------------------------------------------------------------------
__global__ void pack_kernel(const float* __restrict__ A) {
    int node = threadIdx.x;            // lanes -> consecutive addresses
    int bw   = blockIdx.x;
    int b    = bw >> 2;
    int w    = bw & 3;
    const float* Ab = A + (size_t)b * NN * NN;
    unsigned int word = 0;
#pragma unroll
    for (int j = 0; j < 32; j++) {
        float v = __ldg(&Ab[(size_t)(w * 32 + j) * NN + node]);
        word |= (v != 0.0f ? 1u : 0u) << j;
    }
    g_packed[((size_t)(b * NN + node) << 2) + w] = word;
}

// ---------------------------------------------------------------------------
// Kernel 2: sequential per-batch evaluation. One warp per batch element.
// lane = hidden channel (H=32). Register-resident outputs, value+offset
// compaction, double-buffered list, one-step prefetch of all per-node data.
// ---------------------------------------------------------------------------
__global__ __launch_bounds__(WARPS_PER_CTA * 32)
void chain_kernel(const float* __restrict__ x,
                  const float* __restrict__ u,
                  const float* __restrict__ W1,   // (128,129,32)
                  const float* __restrict__ b1,   // (128,32)
                  const float* __restrict__ W2,   // (128,32,1)
                  const float* __restrict__ b2,   // (128,1)
                  const int*   __restrict__ order,   // (B,128)
                  const int*   __restrict__ do_idxs, // (B,)
                  float* __restrict__ out,        // (B,128)
                  int B)
{
    // double-buffered compacted list: {o_value, w1_byte_offset_bits}
    __shared__ float2 s_list[WARPS_PER_CTA][2][132];
    __shared__ int    s_ord [WARPS_PER_CTA][NN];

    const int warp = threadIdx.x >> 5;
    const int lane = threadIdx.x & 31;
    const int b    = blockIdx.x * WARPS_PER_CTA + warp;
    if (b >= B) return;

    int* sord = s_ord[warp];

    const int   do_idx = do_idxs[b];
    const float ub     = u[b];
    const float* xb    = x + (size_t)b * NN;

    // outputs (so*) and x row (xr*) in registers; order row in smem
    float so0, so1, so2, so3;
    float xr0, xr1, xr2, xr3;
    {
        int d0 = lane, d1 = 32 + lane, d2 = 64 + lane, d3 = 96 + lane;
        so0 = (d0 == do_idx) ? ub : 0.0f;
        so1 = (d1 == do_idx) ? ub : 0.0f;
        so2 = (d2 == do_idx) ? ub : 0.0f;
        so3 = (d3 == do_idx) ? ub : 0.0f;
        xr0 = __ldg(&xb[d0]); xr1 = __ldg(&xb[d1]);
        xr2 = __ldg(&xb[d2]); xr3 = __ldg(&xb[d3]);
        const int* ob = order + (size_t)b * NN;
        sord[d0] = __ldg(&ob[d0]); sord[d1] = __ldg(&ob[d1]);
        sord[d2] = __ldg(&ob[d2]); sord[d3] = __ldg(&ob[d3]);
    }
    // per-lane W1 byte offsets for each owned d (d * NH * 4 bytes)
    const int off0 = lane * 128;
    const int off1 = off0 + 4096;
    const int off2 = off0 + 8192;
    const int off3 = off0 + 12288;

    // nonzero-outputs bitmask (warp-uniform)
    unsigned int nz0 = 0, nz1 = 0, nz2 = 0, nz3 = 0;
    if (do_idx >= 0) {
        unsigned int bit = 1u << (do_idx & 31);
        if      ((do_idx >> 5) == 0) nz0 = bit;
        else if ((do_idx >> 5) == 1) nz1 = bit;
        else if ((do_idx >> 5) == 2) nz2 = bit;
        else                         nz3 = bit;
    }

    const uint4* pk = reinterpret_cast<const uint4*>(g_packed + (size_t)b * NN * 4);
    const unsigned int lanebit = 1u << lane;
    const unsigned int below   = lanebit - 1u;

    __syncwarp();

    // ---- prefetch state for step 0 ----
    int          node_p = sord[0];
    const float* w1_p   = W1 + (size_t)node_p * 129 * NH + lane;
    uint4        mw_p   = __ldg(&pk[node_p]);
    float        b1_p   = __ldg(&b1[node_p * NH + lane]);
    float        w2_p   = __ldg(&W2[node_p * NH + lane]);
    float        b2_p   = __ldg(&b2[node_p]);
    float        wx_p   = __ldg(&w1_p[128 * NH]);

    for (int t = 0; t < NN; t++) {
        // consume prefetched state
        const int    node = node_p;
        const uint4  mw   = mw_p;
        const float* w1n  = w1_p;
        const float  b1v  = b1_p, w2v = w2_p, b2v = b2_p, wxv = wx_p;

        // issue prefetch for t+1 (overlaps with this step's body)
        if (t + 1 < NN) {
            node_p = sord[t + 1];
            w1_p   = W1 + (size_t)node_p * 129 * NH + lane;
            mw_p   = __ldg(&pk[node_p]);
            b1_p   = __ldg(&b1[node_p * NH + lane]);
            w2_p   = __ldg(&W2[node_p * NH + lane]);
            b2_p   = __ldg(&b2[node_p]);
            wx_p   = __ldg(&w1_p[128 * NH]);
        }

        if (node != do_idx) {
            unsigned int m0 = mw.x & nz0;
            unsigned int m1 = mw.y & nz1;
            unsigned int m2 = mw.z & nz2;
            unsigned int m3 = mw.w & nz3;
            int c0 = __popc(m0), c1 = __popc(m1), c2 = __popc(m2), c3 = __popc(m3);
            const int cnt = c0 + c1 + c2 + c3;

            float2* buf = s_list[warp][t & 1];
            if (m0 & lanebit) buf[            __popc(m0 & below)] = make_float2(so0, __int_as_float(off0));
            if (m1 & lanebit) buf[c0 +        __popc(m1 & below)] = make_float2(so1, __int_as_float(off1));
            if (m2 & lanebit) buf[c0+c1 +     __popc(m2 & below)] = make_float2(so2, __int_as_float(off2));
            if (m3 & lanebit) buf[c0+c1+c2 +  __popc(m3 & below)] = make_float2(so3, __int_as_float(off3));
            if (lane < 3)     buf[cnt + lane] = make_float2(0.0f, __int_as_float(0));
            __syncwarp();

            // x fetch via register shuffle (node is warp-uniform)
            int wsel = node >> 5;
            float xs = (wsel == 0) ? xr0 : (wsel == 1) ? xr1 : (wsel == 2) ? xr2 : xr3;
            float xv = __shfl_sync(0xffffffffu, xs, node & 31);

            float acc = fmaf(xv, wxv, b1v);

            const float4* bf4 = reinterpret_cast<const float4*>(buf);
            const char*   wb  = reinterpret_cast<const char*>(w1n);
            const int iters = (cnt + 3) >> 2;
            for (int it = 0; it < iters; it++) {
                float4 pa = bf4[it * 2];       // {o0, off0, o1, off1}
                float4 pb = bf4[it * 2 + 1];   // {o2, off2, o3, off3}
                float v0 = __ldg(reinterpret_cast<const float*>(wb + __float_as_int(pa.y)));
                float v1 = __ldg(reinterpret_cast<const float*>(wb + __float_as_int(pa.w)));
                float v2 = __ldg(reinterpret_cast<const float*>(wb + __float_as_int(pb.y)));
                float v3 = __ldg(reinterpret_cast<const float*>(wb + __float_as_int(pb.w)));
                acc = fmaf(pa.x, v0, acc);
                acc = fmaf(pa.z, v1, acc);
                acc = fmaf(pb.x, v2, acc);
                acc = fmaf(pb.z, v3, acc);
            }

            // leaky_relu (slope 0.01), then 32->1 dot via butterfly reduce
            float h = acc > 0.0f ? acc : 0.01f * acc;
            float p = h * w2v;
            p += __shfl_xor_sync(0xffffffffu, p, 16);
            p += __shfl_xor_sync(0xffffffffu, p, 8);
            p += __shfl_xor_sync(0xffffffffu, p, 4);
            p += __shfl_xor_sync(0xffffffffu, p, 2);
            p += __shfl_xor_sync(0xffffffffu, p, 1);
            float outv = p + b2v;   // all lanes hold the result

            // register-resident outputs update (no STS, no extra sync)
            if ((node & 31) == lane) {
                if      (wsel == 0) so0 = outv;
                else if (wsel == 1) so1 = outv;
                else if (wsel == 2) so2 = outv;
                else                so3 = outv;
            }
        }

        // mark node as now-defined (uniform update)
        unsigned int bit = 1u << (node & 31);
        int ws = node >> 5;
        if      (ws == 0) nz0 |= bit;
        else if (ws == 1) nz1 |= bit;
        else if (ws == 2) nz2 |= bit;
        else              nz3 |= bit;
    }

    out[(size_t)b * NN +       lane] = so0;
    out[(size_t)b * NN +  32 + lane] = so1;
    out[(size_t)b * NN +  64 + lane] = so2;
    out[(size_t)b * NN +  96 + lane] = so3;
}

// ---------------------------------------------------------------------------
// inputs (metadata order): x, A, u, W1, b1, W2, b2, order, do_idxs
// ---------------------------------------------------------------------------
extern "C" void kernel_launch(void* const* d_in, const int* in_sizes, int n_in,
                              void* d_out, int out_size) {
    const float* x   = (const float*)d_in[0];
    const float* A   = (const float*)d_in[1];
    const float* u   = (const float*)d_in[2];
    const float* W1  = (const float*)d_in[3];
    const float* b1  = (const float*)d_in[4];
    const float* W2  = (const float*)d_in[5];
    const float* b2  = (const float*)d_in[6];
    const int*   ord = (const int*)d_in[7];
    const int*   doi = (const int*)d_in[8];
    float* out = (float*)d_out;

    int B = in_sizes[2];              // size of u = batch
    if (B > NB) B = NB;               // g_packed capacity (fixed problem size)

    pack_kernel<<<B * 4, 128>>>(A);

    int grid = (B + WARPS_PER_CTA - 1) / WARPS_PER_CTA;
    chain_kernel<<<grid, WARPS_PER_CTA * 32>>>(x, u, W1, b1, W2, b2, ord, doi, out, B);
}